// round 1
// baseline (speedup 1.0000x reference)
#include <cuda_runtime.h>
#include <mma.h>
using namespace nvcuda;

// Problem constants (fixed by setup_inputs)
#define BATCH   32
#define SLEN    4096
#define DMODEL  512
#define NHEADS  8
#define HD      64
#define WIN     128
#define SHIFT   64
#define NWB     32            // windows per batch
#define NWIN    1024          // total windows (BATCH * NWB)

// Scratch: qkv in [part(q/k/v)][win][head][row][d] layout, plus attention output
__device__ __align__(16) float g_qkv[3u * NWIN * NHEADS * WIN * HD]; // 805 MB
__device__ __align__(16) float g_o[(size_t)NWIN * WIN * DMODEL];     // 268 MB

using AFrag  = wmma::fragment<wmma::matrix_a, 16, 16, 8, wmma::precision::tf32, wmma::row_major>;
using BFragC = wmma::fragment<wmma::matrix_b, 16, 16, 8, wmma::precision::tf32, wmma::col_major>;
using BFragR = wmma::fragment<wmma::matrix_b, 16, 16, 8, wmma::precision::tf32, wmma::row_major>;
using CFrag  = wmma::fragment<wmma::accumulator, 16, 16, 8, float>;

// 3xTF32 split: v = hi + lo, both rounded to tf32. hi*hi + hi*lo + lo*hi ~ fp32 accuracy.
template <class Frag>
__device__ __forceinline__ void split3(const Frag& f, Frag& hi, Frag& lo) {
#pragma unroll
    for (int i = 0; i < f.num_elements; i++) {
        float v = f.x[i];
        float h = wmma::__float_to_tf32(v);
        hi.x[i] = h;
        lo.x[i] = wmma::__float_to_tf32(v - h);
    }
}

template <class FA, class FB>
__device__ __forceinline__ void mma3(CFrag& acc, const FA& ah, const FA& al,
                                     const FB& bh, const FB& bl) {
    wmma::mma_sync(acc, al, bh, acc);   // small terms first
    wmma::mma_sync(acc, ah, bl, acc);
    wmma::mma_sync(acc, ah, bh, acc);
}

// ============================================================================
// K1: QKV projection. C[131072,1536] = Xrolled @ w_in^T + b_in
// Block tile 128 rows (one window) x 64 cols, K chunks of 32.
// Scatters into g_qkv [p][w][h][r][d].
// ============================================================================
__global__ __launch_bounds__(256) void k_qkv(const float* __restrict__ x,
                                             const float* __restrict__ w_in,
                                             const float* __restrict__ b_in) {
    const int n0  = blockIdx.x * 64;     // output column base (col tiles fastest -> L2 reuse of A)
    const int w   = blockIdx.y;          // window id
    const int tid = threadIdx.x;
    const int warp = tid >> 5;
    const int wr = warp >> 1, wc = warp & 1;

    extern __shared__ float sm[];
    float* As = sm;             // [128][36]
    float* Bs = sm + 128 * 36;  // [64][36]

    const int b = w >> 5, j = w & 31;
    const float* xb = x + (size_t)b * SLEN * DMODEL;

    CFrag acc[2][2];
#pragma unroll
    for (int i = 0; i < 2; i++)
#pragma unroll
        for (int jj = 0; jj < 2; jj++) wmma::fill_fragment(acc[i][jj], 0.0f);

    for (int k0 = 0; k0 < DMODEL; k0 += 32) {
#pragma unroll
        for (int t = tid; t < 128 * 32; t += 256) {
            int r = t >> 5, k = t & 31;
            int sp = (j * WIN + r + SHIFT) & (SLEN - 1);  // roll(-shift) gather
            As[r * 36 + k] = xb[(size_t)sp * DMODEL + k0 + k];
        }
#pragma unroll
        for (int t = tid; t < 64 * 32; t += 256) {
            int n = t >> 5, k = t & 31;
            Bs[n * 36 + k] = w_in[(size_t)(n0 + n) * DMODEL + k0 + k];
        }
        __syncthreads();
#pragma unroll
        for (int ks = 0; ks < 32; ks += 8) {
            AFrag  ah[2], al[2];
            BFragC bh[2], bl[2];
#pragma unroll
            for (int i = 0; i < 2; i++) {
                AFrag t; wmma::load_matrix_sync(t, As + (wr * 32 + i * 16) * 36 + ks, 36);
                split3(t, ah[i], al[i]);
            }
#pragma unroll
            for (int jj = 0; jj < 2; jj++) {
                BFragC t; wmma::load_matrix_sync(t, Bs + (wc * 32 + jj * 16) * 36 + ks, 36);
                split3(t, bh[jj], bl[jj]);
            }
#pragma unroll
            for (int i = 0; i < 2; i++)
#pragma unroll
                for (int jj = 0; jj < 2; jj++)
                    mma3(acc[i][jj], ah[i], al[i], bh[jj], bl[jj]);
        }
        __syncthreads();
    }

    // Stage C through smem (reuses As/Bs region), add bias, scatter to g_qkv
    float* Cs = sm;  // [128][68]
#pragma unroll
    for (int i = 0; i < 2; i++)
#pragma unroll
        for (int jj = 0; jj < 2; jj++)
            wmma::store_matrix_sync(Cs + (wr * 32 + i * 16) * 68 + wc * 32 + jj * 16,
                                    acc[i][jj], 68, wmma::mem_row_major);
    __syncthreads();

    const int p = n0 >> 9;              // 0=Q, 1=K, 2=V
    const int h = (n0 >> 6) & 7;        // head (64-col block fits one head)
    float* dst = g_qkv + (((size_t)p * NWIN + w) * NHEADS + h) * (WIN * HD);
#pragma unroll
    for (int t = tid; t < 2048; t += 256) {   // 2048 float4 = 128x64
        int r = t >> 4, d4 = (t & 15) << 2;
        float4 v;
        v.x = Cs[r * 68 + d4 + 0] + b_in[n0 + d4 + 0];
        v.y = Cs[r * 68 + d4 + 1] + b_in[n0 + d4 + 1];
        v.z = Cs[r * 68 + d4 + 2] + b_in[n0 + d4 + 2];
        v.w = Cs[r * 68 + d4 + 3] + b_in[n0 + d4 + 3];
        *reinterpret_cast<float4*>(dst + r * HD + d4) = v;
    }
}

// ============================================================================
// K2: per (window, head) attention. S = QK^T/8, softmax, O = P V.
// smem: Q[128][68] K[128][68] V[128][68]; P[128][132] overlays Q+K.
// ============================================================================
__global__ __launch_bounds__(256) void k_attn() {
    const int w = blockIdx.x;
    const int h = blockIdx.y;
    const int tid  = threadIdx.x;
    const int warp = tid >> 5, lane = tid & 31;

    extern __shared__ float sm[];
    float* Qs = sm;            // [128][68] = 8704 floats
    float* Ks = sm + 8704;
    float* Vs = sm + 17408;
    float* Ps = sm;            // [128][132] = 16896 floats, overlays Qs+Ks

    const size_t base = ((size_t)w * NHEADS + h) * (WIN * HD);
    const size_t part = (size_t)NWIN * NHEADS * WIN * HD;
    const float* qg = g_qkv + base;
    const float* kg = g_qkv + part + base;
    const float* vg = g_qkv + 2 * part + base;

#pragma unroll
    for (int t = tid; t < WIN * HD; t += 256) {
        int r = t >> 6, d = t & 63;
        Qs[r * 68 + d] = qg[t];
        Ks[r * 68 + d] = kg[t];
        Vs[r * 68 + d] = vg[t];
    }
    __syncthreads();

    // ---- S = Q K^T, scaled by 1/sqrt(64) ----
    {
        const int wr = warp >> 1, wc = warp & 1;  // 4 row-groups x 2 col-groups (32 x 64 per warp)
        CFrag acc[2][4];
#pragma unroll
        for (int i = 0; i < 2; i++)
#pragma unroll
            for (int jj = 0; jj < 4; jj++) wmma::fill_fragment(acc[i][jj], 0.0f);

#pragma unroll
        for (int kk = 0; kk < HD; kk += 8) {
            AFrag  ah[2], al[2];
            BFragC bh[4], bl[4];
#pragma unroll
            for (int i = 0; i < 2; i++) {
                AFrag t; wmma::load_matrix_sync(t, Qs + (wr * 32 + i * 16) * 68 + kk, 68);
                split3(t, ah[i], al[i]);
            }
#pragma unroll
            for (int jj = 0; jj < 4; jj++) {
                BFragC t; wmma::load_matrix_sync(t, Ks + (wc * 64 + jj * 16) * 68 + kk, 68);
                split3(t, bh[jj], bl[jj]);
            }
#pragma unroll
            for (int i = 0; i < 2; i++)
#pragma unroll
                for (int jj = 0; jj < 4; jj++)
                    mma3(acc[i][jj], ah[i], al[i], bh[jj], bl[jj]);
        }
        __syncthreads();  // all warps done reading Qs/Ks before P overwrites them
#pragma unroll
        for (int i = 0; i < 2; i++)
#pragma unroll
            for (int jj = 0; jj < 4; jj++) {
#pragma unroll
                for (int e = 0; e < acc[i][jj].num_elements; e++) acc[i][jj].x[e] *= 0.125f;
                wmma::store_matrix_sync(Ps + (wr * 32 + i * 16) * 132 + wc * 64 + jj * 16,
                                        acc[i][jj], 132, wmma::mem_row_major);
            }
    }
    __syncthreads();

    // ---- exact softmax over 128 cols, one warp per 16 rows ----
#pragma unroll
    for (int rr = 0; rr < 16; rr++) {
        float* row = Ps + (warp * 16 + rr) * 132;
        float v0 = row[lane], v1 = row[lane + 32], v2 = row[lane + 64], v3 = row[lane + 96];
        float m = fmaxf(fmaxf(v0, v1), fmaxf(v2, v3));
#pragma unroll
        for (int o = 16; o; o >>= 1) m = fmaxf(m, __shfl_xor_sync(0xffffffffu, m, o));
        v0 = __expf(v0 - m); v1 = __expf(v1 - m); v2 = __expf(v2 - m); v3 = __expf(v3 - m);
        float s = v0 + v1 + v2 + v3;
#pragma unroll
        for (int o = 16; o; o >>= 1) s += __shfl_xor_sync(0xffffffffu, s, o);
        float inv = 1.0f / s;
        row[lane] = v0 * inv; row[lane + 32] = v1 * inv;
        row[lane + 64] = v2 * inv; row[lane + 96] = v3 * inv;
    }
    __syncthreads();

    // ---- O = P V, store straight to g_o [131072, 512] ----
    {
        const int wr = warp >> 1, wc = warp & 1;  // 32 x 32 per warp
        CFrag acc[2][2];
#pragma unroll
        for (int i = 0; i < 2; i++)
#pragma unroll
            for (int jj = 0; jj < 2; jj++) wmma::fill_fragment(acc[i][jj], 0.0f);

#pragma unroll
        for (int kk = 0; kk < WIN; kk += 8) {
            AFrag  ah[2], al[2];
            BFragR bh[2], bl[2];
#pragma unroll
            for (int i = 0; i < 2; i++) {
                AFrag t; wmma::load_matrix_sync(t, Ps + (wr * 32 + i * 16) * 132 + kk, 132);
                split3(t, ah[i], al[i]);
            }
#pragma unroll
            for (int jj = 0; jj < 2; jj++) {
                BFragR t; wmma::load_matrix_sync(t, Vs + kk * 68 + wc * 32 + jj * 16, 68);
                split3(t, bh[jj], bl[jj]);
            }
#pragma unroll
            for (int i = 0; i < 2; i++)
#pragma unroll
                for (int jj = 0; jj < 2; jj++)
                    mma3(acc[i][jj], ah[i], al[i], bh[jj], bl[jj]);
        }
        float* og = g_o + (size_t)w * WIN * DMODEL + (size_t)h * HD;
#pragma unroll
        for (int i = 0; i < 2; i++)
#pragma unroll
            for (int jj = 0; jj < 2; jj++)
                wmma::store_matrix_sync(og + (wr * 32 + i * 16) * DMODEL + wc * 32 + jj * 16,
                                        acc[i][jj], DMODEL, wmma::mem_row_major);
    }
}

// ============================================================================
// K3: output projection. out = roll(g_o @ w_out^T + b_out, +shift)
// ============================================================================
__global__ __launch_bounds__(256) void k_out(const float* __restrict__ w_out,
                                             const float* __restrict__ b_out,
                                             float* __restrict__ out) {
    const int n0  = blockIdx.x * 64;
    const int w   = blockIdx.y;
    const int tid = threadIdx.x;
    const int warp = tid >> 5;
    const int wr = warp >> 1, wc = warp & 1;

    extern __shared__ float sm[];
    float* As = sm;             // [128][36]
    float* Bs = sm + 128 * 36;  // [64][36]

    const float* ag = g_o + (size_t)w * WIN * DMODEL;

    CFrag acc[2][2];
#pragma unroll
    for (int i = 0; i < 2; i++)
#pragma unroll
        for (int jj = 0; jj < 2; jj++) wmma::fill_fragment(acc[i][jj], 0.0f);

    for (int k0 = 0; k0 < DMODEL; k0 += 32) {
#pragma unroll
        for (int t = tid; t < 128 * 32; t += 256) {
            int r = t >> 5, k = t & 31;
            As[r * 36 + k] = ag[(size_t)r * DMODEL + k0 + k];
        }
#pragma unroll
        for (int t = tid; t < 64 * 32; t += 256) {
            int n = t >> 5, k = t & 31;
            Bs[n * 36 + k] = w_out[(size_t)(n0 + n) * DMODEL + k0 + k];
        }
        __syncthreads();
#pragma unroll
        for (int ks = 0; ks < 32; ks += 8) {
            AFrag  ah[2], al[2];
            BFragC bh[2], bl[2];
#pragma unroll
            for (int i = 0; i < 2; i++) {
                AFrag t; wmma::load_matrix_sync(t, As + (wr * 32 + i * 16) * 36 + ks, 36);
                split3(t, ah[i], al[i]);
            }
#pragma unroll
            for (int jj = 0; jj < 2; jj++) {
                BFragC t; wmma::load_matrix_sync(t, Bs + (wc * 32 + jj * 16) * 36 + ks, 36);
                split3(t, bh[jj], bl[jj]);
            }
#pragma unroll
            for (int i = 0; i < 2; i++)
#pragma unroll
                for (int jj = 0; jj < 2; jj++)
                    mma3(acc[i][jj], ah[i], al[i], bh[jj], bl[jj]);
        }
        __syncthreads();
    }

    float* Cs = sm;  // [128][68]
#pragma unroll
    for (int i = 0; i < 2; i++)
#pragma unroll
        for (int jj = 0; jj < 2; jj++)
            wmma::store_matrix_sync(Cs + (wr * 32 + i * 16) * 68 + wc * 32 + jj * 16,
                                    acc[i][jj], 68, wmma::mem_row_major);
    __syncthreads();

    const int b = w >> 5, j = w & 31;
#pragma unroll
    for (int t = tid; t < 2048; t += 256) {
        int r = t >> 4, d4 = (t & 15) << 2;
        int sp = (j * WIN + r + SHIFT) & (SLEN - 1);  // roll(+shift) scatter
        float4 v;
        v.x = Cs[r * 68 + d4 + 0] + b_out[n0 + d4 + 0];
        v.y = Cs[r * 68 + d4 + 1] + b_out[n0 + d4 + 1];
        v.z = Cs[r * 68 + d4 + 2] + b_out[n0 + d4 + 2];
        v.w = Cs[r * 68 + d4 + 3] + b_out[n0 + d4 + 3];
        *reinterpret_cast<float4*>(out + ((size_t)b * SLEN + sp) * DMODEL + n0 + d4) = v;
    }
}

// ============================================================================
extern "C" void kernel_launch(void* const* d_in, const int* in_sizes, int n_in,
                              void* d_out, int out_size) {
    const float* x     = (const float*)d_in[0];
    const float* w_in  = (const float*)d_in[1];
    const float* b_in  = (const float*)d_in[2];
    const float* w_out = (const float*)d_in[3];
    const float* b_out = (const float*)d_in[4];
    // d_in[5] = window_size (128), d_in[6] = shift_size (64): compile-time constants
    float* out = (float*)d_out;

    const int GEMM_SMEM = 34816;        // max(load tiles 27648, C stage 34816)
    const int ATTN_SMEM = 26112 * 4;    // Q+K+V [128][68] x3 = 104448 B

    cudaFuncSetAttribute(k_attn, cudaFuncAttributeMaxDynamicSharedMemorySize, ATTN_SMEM);

    k_qkv<<<dim3(24, NWIN), 256, GEMM_SMEM>>>(x, w_in, b_in);
    k_attn<<<dim3(NWIN, NHEADS), 256, ATTN_SMEM>>>();
    k_out<<<dim3(8, NWIN), 256, GEMM_SMEM>>>(w_out, b_out, out);
}

// round 3
// speedup vs baseline: 3.1992x; 3.1992x over previous
#include <cuda_runtime.h>
#include <cuda_fp16.h>
#include <mma.h>
#include <cstdint>
using namespace nvcuda;

// Problem constants (fixed by setup_inputs)
#define BATCH   32
#define SLEN    4096
#define DMODEL  512
#define NHEADS  8
#define HD      64
#define WIN     128
#define SHIFT   64
#define NWIN    1024          // total windows (BATCH * 32)

// ---------------------------------------------------------------------------
// Persistent fp16 hi/lo split arrays (2-way fp16 split ~ 22-bit mantissa)
// ---------------------------------------------------------------------------
__device__ __align__(16) __half g_x_hi[(size_t)BATCH * SLEN * DMODEL];
__device__ __align__(16) __half g_x_lo[(size_t)BATCH * SLEN * DMODEL];
__device__ __align__(16) __half g_win_hi[3 * DMODEL * DMODEL];
__device__ __align__(16) __half g_win_lo[3 * DMODEL * DMODEL];
__device__ __align__(16) __half g_wout_hi[DMODEL * DMODEL];
__device__ __align__(16) __half g_wout_lo[DMODEL * DMODEL];
__device__ __align__(16) __half g_qkv_hi[(size_t)3 * NWIN * NHEADS * WIN * HD];
__device__ __align__(16) __half g_qkv_lo[(size_t)3 * NWIN * NHEADS * WIN * HD];
__device__ __align__(16) __half g_o_hi[(size_t)NWIN * WIN * DMODEL];
__device__ __align__(16) __half g_o_lo[(size_t)NWIN * WIN * DMODEL];

// ---------------------------------------------------------------------------
// wmma fp16 types + 3-product split MMA
// ---------------------------------------------------------------------------
using HA  = wmma::fragment<wmma::matrix_a, 16, 16, 16, __half, wmma::row_major>;
using HBc = wmma::fragment<wmma::matrix_b, 16, 16, 16, __half, wmma::col_major>;
using HBr = wmma::fragment<wmma::matrix_b, 16, 16, 16, __half, wmma::row_major>;
using CF  = wmma::fragment<wmma::accumulator, 16, 16, 16, float>;

template <class FB>
__device__ __forceinline__ void mma3(CF& acc, const HA& ah, const HA& al,
                                     const FB& bh, const FB& bl) {
    wmma::mma_sync(acc, al, bh, acc);
    wmma::mma_sync(acc, ah, bl, acc);
    wmma::mma_sync(acc, ah, bh, acc);
}

__device__ __forceinline__ void split_store4(const float4 v, __half* hi, __half* lo) {
    __half hx = __float2half_rn(v.x), hy = __float2half_rn(v.y);
    __half hz = __float2half_rn(v.z), hw = __float2half_rn(v.w);
    *reinterpret_cast<__half2*>(hi)     = __halves2half2(hx, hy);
    *reinterpret_cast<__half2*>(hi + 2) = __halves2half2(hz, hw);
    __half lx = __float2half_rn(v.x - __half2float(hx));
    __half ly = __float2half_rn(v.y - __half2float(hy));
    __half lz = __float2half_rn(v.z - __half2float(hz));
    __half lw = __float2half_rn(v.w - __half2float(hw));
    *reinterpret_cast<__half2*>(lo)     = __halves2half2(lx, ly);
    *reinterpret_cast<__half2*>(lo + 2) = __halves2half2(lz, lw);
}

// ---------------------------------------------------------------------------
// Prep: split fp32 source arrays into fp16 hi/lo
// which: 0 = x, 1 = w_in, 2 = w_out
// ---------------------------------------------------------------------------
__global__ void k_split(const float4* __restrict__ src, int which, int n4) {
    int i = blockIdx.x * blockDim.x + threadIdx.x;
    if (i >= n4) return;
    __half *hi, *lo;
    if (which == 0)      { hi = g_x_hi;    lo = g_x_lo; }
    else if (which == 1) { hi = g_win_hi;  lo = g_win_lo; }
    else                 { hi = g_wout_hi; lo = g_wout_lo; }
    float4 v = src[i];
    split_store4(v, hi + (size_t)i * 4, lo + (size_t)i * 4);
}

// ---------------------------------------------------------------------------
// Projection GEMM: C[128x128] per CTA, fp16-split wmma.
// MODE 0: A = rolled x (hi/lo), W = w_in  -> split-store to g_qkv_hi/lo (+b_in)
// MODE 1: A = g_o (hi/lo),     W = w_out -> fp32 out with roll(+shift) (+b_out)
// smem: Ah/Al/Bh/Bl [128][72] halves (73728 B); Cs fp32 [128][132] overlays.
// ---------------------------------------------------------------------------
#define PROJ_SMEM 73728

template <int MODE>
__global__ __launch_bounds__(256, 2) void k_proj(const float* __restrict__ bias,
                                                 float* __restrict__ outp) {
    extern __shared__ char smem[];
    __half* Ah = (__half*)smem;            // [128][72]
    __half* Al = Ah + 9216;
    __half* Bh = Ah + 18432;
    __half* Bl = Ah + 27648;
    float*  Cs = (float*)smem;             // [128][132]

    const int tid  = threadIdx.x;
    const int warp = tid >> 5;
    const int wr = warp >> 1, wc = warp & 1;
    const int n0 = blockIdx.x * 128;
    const int w  = blockIdx.y;
    const int b  = w >> 5, j = w & 31;

    const __half* Asrc_h = (MODE == 0) ? g_x_hi : g_o_hi;
    const __half* Asrc_l = (MODE == 0) ? g_x_lo : g_o_lo;
    const __half* Bsrc_h = (MODE == 0) ? g_win_hi : g_wout_hi;
    const __half* Bsrc_l = (MODE == 0) ? g_win_lo : g_wout_lo;

    // load mapping: 2 threads per row, 32 halves each
    const int lr = tid >> 1, cg = (tid & 1) * 32;
    size_t arow;
    if (MODE == 0) {
        int sp = (j * WIN + lr + SHIFT) & (SLEN - 1);      // roll(-shift) gather
        arow = ((size_t)b * SLEN + sp) * DMODEL;
    } else {
        arow = ((size_t)w * WIN + lr) * DMODEL;
    }
    const size_t brow = (size_t)(n0 + lr) * DMODEL;

    CF acc[2][4];
#pragma unroll
    for (int i = 0; i < 2; i++)
#pragma unroll
        for (int jj = 0; jj < 4; jj++) wmma::fill_fragment(acc[i][jj], 0.0f);

    for (int c = 0; c < 8; c++) {          // K chunks of 64 halves
        uint4 va_h[4], va_l[4], vb_h[4], vb_l[4];
        const uint4* pAh = (const uint4*)(Asrc_h + arow + c * 64 + cg);
        const uint4* pAl = (const uint4*)(Asrc_l + arow + c * 64 + cg);
        const uint4* pBh = (const uint4*)(Bsrc_h + brow + c * 64 + cg);
        const uint4* pBl = (const uint4*)(Bsrc_l + brow + c * 64 + cg);
#pragma unroll
        for (int q = 0; q < 4; q++) { va_h[q] = pAh[q]; va_l[q] = pAl[q]; }
#pragma unroll
        for (int q = 0; q < 4; q++) { vb_h[q] = pBh[q]; vb_l[q] = pBl[q]; }
        __syncthreads();                   // previous chunk's frag loads done
#pragma unroll
        for (int q = 0; q < 4; q++) {
            *(uint4*)&Ah[lr * 72 + cg + q * 8] = va_h[q];
            *(uint4*)&Al[lr * 72 + cg + q * 8] = va_l[q];
            *(uint4*)&Bh[lr * 72 + cg + q * 8] = vb_h[q];
            *(uint4*)&Bl[lr * 72 + cg + q * 8] = vb_l[q];
        }
        __syncthreads();
#pragma unroll
        for (int ks = 0; ks < 4; ks++) {   // 4 x k16
            HA ah[2], al[2];
#pragma unroll
            for (int i = 0; i < 2; i++) {
                wmma::load_matrix_sync(ah[i], Ah + (wr * 32 + i * 16) * 72 + ks * 16, 72);
                wmma::load_matrix_sync(al[i], Al + (wr * 32 + i * 16) * 72 + ks * 16, 72);
            }
#pragma unroll
            for (int jj = 0; jj < 4; jj++) {
                HBc bh, bl;
                wmma::load_matrix_sync(bh, Bh + (wc * 64 + jj * 16) * 72 + ks * 16, 72);
                wmma::load_matrix_sync(bl, Bl + (wc * 64 + jj * 16) * 72 + ks * 16, 72);
#pragma unroll
                for (int i = 0; i < 2; i++) mma3(acc[i][jj], ah[i], al[i], bh, bl);
            }
        }
    }

    __syncthreads();
#pragma unroll
    for (int i = 0; i < 2; i++)
#pragma unroll
        for (int jj = 0; jj < 4; jj++)
            wmma::store_matrix_sync(Cs + (wr * 32 + i * 16) * 132 + wc * 64 + jj * 16,
                                    acc[i][jj], 132, wmma::mem_row_major);
    __syncthreads();

#pragma unroll
    for (int it = 0; it < 16; it++) {
        int idx = tid + it * 256;          // over 128 x 32 col-groups
        int r = idx >> 5, cc = (idx & 31) * 4;
        float4 v;
        v.x = Cs[r * 132 + cc + 0] + bias[n0 + cc + 0];
        v.y = Cs[r * 132 + cc + 1] + bias[n0 + cc + 1];
        v.z = Cs[r * 132 + cc + 2] + bias[n0 + cc + 2];
        v.w = Cs[r * 132 + cc + 3] + bias[n0 + cc + 3];
        if (MODE == 0) {
            int gc = n0 + cc;
            int p = gc >> 9, hh = (gc >> 6) & 7, d = gc & 63;
            size_t o = ((((size_t)p * NWIN + w) * NHEADS + hh) * WIN + r) * HD + d;
            split_store4(v, g_qkv_hi + o, g_qkv_lo + o);
        } else {
            int sp = (j * WIN + r + SHIFT) & (SLEN - 1);   // roll(+shift) scatter
            *(float4*)(outp + ((size_t)b * SLEN + sp) * DMODEL + n0 + cc) = v;
        }
    }
}

// ---------------------------------------------------------------------------
// Attention: one CTA per (window, head). 512 threads, 1 CTA/SM.
// smem map (bytes):
//   [0, 73728)        Qh/Ql/Kh/Kl [128][72] halves -> later Ps fp32 [128][132]
//                      -> later Os fp32 [128][68]
//   [73728, 110592)   Vh/Vl [128][72]
//   [110592, 180224)  Ph/Pl [128][136] halves
// ---------------------------------------------------------------------------
#define ATTN_SMEM 180224

__global__ __launch_bounds__(512, 1) void k_attn() {
    extern __shared__ char smem[];
    __half* Qh = (__half*)smem;
    __half* Ql = Qh + 9216;
    __half* Kh = Qh + 18432;
    __half* Kl = Qh + 27648;
    float*  Ps = (float*)smem;                       // [128][132]
    __half* Vh = (__half*)(smem + 73728);
    __half* Vl = Vh + 9216;
    __half* Ph = (__half*)(smem + 110592);           // [128][136]
    __half* Pl = Ph + 17408;
    float*  Os = (float*)smem;                       // [128][68]

    const int w = blockIdx.x, h = blockIdx.y;
    const int tid = threadIdx.x;
    const int warp = tid >> 5, lane = tid & 31;

    const size_t part = (size_t)NWIN * NHEADS * WIN * HD;
    const size_t bq = ((size_t)w * NHEADS + h) * (WIN * HD);

    // loads: 4 threads per row, 16 halves (2 x uint4) each
    {
        const int r = tid >> 2, cg = (tid & 3) * 16;
        const size_t so = bq + (size_t)r * HD + cg;
        const int dst = r * 72 + cg;
        *(uint4*)&Qh[dst]     = *(const uint4*)(g_qkv_hi + so);
        *(uint4*)&Qh[dst + 8] = *(const uint4*)(g_qkv_hi + so + 8);
        *(uint4*)&Ql[dst]     = *(const uint4*)(g_qkv_lo + so);
        *(uint4*)&Ql[dst + 8] = *(const uint4*)(g_qkv_lo + so + 8);
        *(uint4*)&Kh[dst]     = *(const uint4*)(g_qkv_hi + part + so);
        *(uint4*)&Kh[dst + 8] = *(const uint4*)(g_qkv_hi + part + so + 8);
        *(uint4*)&Kl[dst]     = *(const uint4*)(g_qkv_lo + part + so);
        *(uint4*)&Kl[dst + 8] = *(const uint4*)(g_qkv_lo + part + so + 8);
        *(uint4*)&Vh[dst]     = *(const uint4*)(g_qkv_hi + 2 * part + so);
        *(uint4*)&Vh[dst + 8] = *(const uint4*)(g_qkv_hi + 2 * part + so + 8);
        *(uint4*)&Vl[dst]     = *(const uint4*)(g_qkv_lo + 2 * part + so);
        *(uint4*)&Vl[dst + 8] = *(const uint4*)(g_qkv_lo + 2 * part + so + 8);
    }
    __syncthreads();

    // ---- S = Q K^T / 8 : 16 warps in 4x4 grid, 32x32 warp tiles ----
    {
        const int wrS = warp >> 2, wcS = warp & 3;
        CF sacc[2][2];
#pragma unroll
        for (int i = 0; i < 2; i++)
#pragma unroll
            for (int jj = 0; jj < 2; jj++) wmma::fill_fragment(sacc[i][jj], 0.0f);
#pragma unroll
        for (int kk = 0; kk < 4; kk++) {
            HA qh2[2], ql2[2];
#pragma unroll
            for (int i = 0; i < 2; i++) {
                wmma::load_matrix_sync(qh2[i], Qh + (wrS * 32 + i * 16) * 72 + kk * 16, 72);
                wmma::load_matrix_sync(ql2[i], Ql + (wrS * 32 + i * 16) * 72 + kk * 16, 72);
            }
#pragma unroll
            for (int jj = 0; jj < 2; jj++) {
                HBc kh2, kl2;
                wmma::load_matrix_sync(kh2, Kh + (wcS * 32 + jj * 16) * 72 + kk * 16, 72);
                wmma::load_matrix_sync(kl2, Kl + (wcS * 32 + jj * 16) * 72 + kk * 16, 72);
#pragma unroll
                for (int i = 0; i < 2; i++) mma3(sacc[i][jj], qh2[i], ql2[i], kh2, kl2);
            }
        }
        __syncthreads();   // Q/K reads complete before Ps overlays
#pragma unroll
        for (int i = 0; i < 2; i++)
#pragma unroll
            for (int jj = 0; jj < 2; jj++) {
#pragma unroll
                for (int e = 0; e < sacc[i][jj].num_elements; e++) sacc[i][jj].x[e] *= 0.125f;
                wmma::store_matrix_sync(Ps + (wrS * 32 + i * 16) * 132 + wcS * 32 + jj * 16,
                                        sacc[i][jj], 132, wmma::mem_row_major);
            }
    }
    __syncthreads();

    // ---- softmax: 16 warps x 8 rows, write fp16 hi/lo P ----
#pragma unroll
    for (int rr = 0; rr < 8; rr++) {
        const int row = warp * 8 + rr;
        const float* prow = Ps + row * 132;
        float v0 = prow[lane], v1 = prow[lane + 32], v2 = prow[lane + 64], v3 = prow[lane + 96];
        float m = fmaxf(fmaxf(v0, v1), fmaxf(v2, v3));
#pragma unroll
        for (int o = 16; o; o >>= 1) m = fmaxf(m, __shfl_xor_sync(0xffffffffu, m, o));
        v0 = __expf(v0 - m); v1 = __expf(v1 - m); v2 = __expf(v2 - m); v3 = __expf(v3 - m);
        float s = v0 + v1 + v2 + v3;
#pragma unroll
        for (int o = 16; o; o >>= 1) s += __shfl_xor_sync(0xffffffffu, s, o);
        float inv = 1.0f / s;
        __half* ph = Ph + row * 136;
        __half* pl = Pl + row * 136;
#pragma unroll
        for (int q = 0; q < 4; q++) {
            float p = ((q == 0) ? v0 : (q == 1) ? v1 : (q == 2) ? v2 : v3) * inv;
            __half hp = __float2half_rn(p);
            ph[lane + q * 32] = hp;
            pl[lane + q * 32] = __float2half_rn(p - __half2float(hp));
        }
    }
    __syncthreads();

    // ---- O = P V : 16 warps in 8x2 grid, 16x32 warp tiles ----
    {
        const int wrP = warp >> 1, wcP = warp & 1;
        CF oacc[2];
        wmma::fill_fragment(oacc[0], 0.0f);
        wmma::fill_fragment(oacc[1], 0.0f);
#pragma unroll
        for (int kk = 0; kk < 8; kk++) {
            HA ph2, pl2;
            wmma::load_matrix_sync(ph2, Ph + (wrP * 16) * 136 + kk * 16, 136);
            wmma::load_matrix_sync(pl2, Pl + (wrP * 16) * 136 + kk * 16, 136);
#pragma unroll
            for (int jj = 0; jj < 2; jj++) {
                HBr vh2, vl2;
                wmma::load_matrix_sync(vh2, Vh + (kk * 16) * 72 + wcP * 32 + jj * 16, 72);
                wmma::load_matrix_sync(vl2, Vl + (kk * 16) * 72 + wcP * 32 + jj * 16, 72);
                mma3(oacc[jj], ph2, pl2, vh2, vl2);
            }
        }
#pragma unroll
        for (int jj = 0; jj < 2; jj++)
            wmma::store_matrix_sync(Os + (wrP * 16) * 68 + wcP * 32 + jj * 16,
                                    oacc[jj], 68, wmma::mem_row_major);
    }
    __syncthreads();

    // ---- split-store O to g_o_hi/lo ----
#pragma unroll
    for (int it = 0; it < 4; it++) {
        int idx = tid + it * 512;          // 128 rows x 16 col-groups
        int r = idx >> 4, cc = (idx & 15) * 4;
        float4 v;
        v.x = Os[r * 68 + cc + 0];
        v.y = Os[r * 68 + cc + 1];
        v.z = Os[r * 68 + cc + 2];
        v.w = Os[r * 68 + cc + 3];
        size_t o = ((size_t)w * WIN + r) * DMODEL + h * HD + cc;
        split_store4(v, g_o_hi + o, g_o_lo + o);
    }
}

// ---------------------------------------------------------------------------
extern "C" void kernel_launch(void* const* d_in, const int* in_sizes, int n_in,
                              void* d_out, int out_size) {
    const float* x     = (const float*)d_in[0];
    const float* w_in  = (const float*)d_in[1];
    const float* b_in  = (const float*)d_in[2];
    const float* w_out = (const float*)d_in[3];
    const float* b_out = (const float*)d_in[4];
    float* out = (float*)d_out;

    cudaFuncSetAttribute(k_proj<0>, cudaFuncAttributeMaxDynamicSharedMemorySize, PROJ_SMEM);
    cudaFuncSetAttribute(k_proj<1>, cudaFuncAttributeMaxDynamicSharedMemorySize, PROJ_SMEM);
    cudaFuncSetAttribute(k_attn,    cudaFuncAttributeMaxDynamicSharedMemorySize, ATTN_SMEM);

    const int n4x = BATCH * SLEN * DMODEL / 4;      // 16,777,216
    const int n4wi = 3 * DMODEL * DMODEL / 4;       // 196,608
    const int n4wo = DMODEL * DMODEL / 4;           // 65,536
    k_split<<<n4x / 256, 256>>>((const float4*)x, 0, n4x);
    k_split<<<n4wi / 256, 256>>>((const float4*)w_in, 1, n4wi);
    k_split<<<n4wo / 256, 256>>>((const float4*)w_out, 2, n4wo);

    k_proj<0><<<dim3(12, NWIN), 256, PROJ_SMEM>>>(b_in, nullptr);
    k_attn<<<dim3(NWIN, NHEADS), 512, ATTN_SMEM>>>();
    k_proj<1><<<dim3(4, NWIN), 256, PROJ_SMEM>>>(b_out, out);
}

// round 4
// speedup vs baseline: 4.1346x; 1.2924x over previous
#include <cuda_runtime.h>
#include <cuda_fp16.h>
#include <mma.h>
#include <cstdint>
using namespace nvcuda;

// Problem constants (fixed by setup_inputs)
#define BATCH   32
#define SLEN    4096
#define DMODEL  512
#define NHEADS  8
#define HD      64
#define WIN     128
#define SHIFT   64
#define NWIN    1024          // total windows (BATCH * 32)

// ---------------------------------------------------------------------------
// Persistent fp16 arrays. Activations (A-side) keep hi/lo split; weights and
// the B-side of attention (K, V) keep hi only (2-term split: (Ah+Al)*Bh).
// ---------------------------------------------------------------------------
__device__ __align__(16) __half g_x_hi[(size_t)BATCH * SLEN * DMODEL];
__device__ __align__(16) __half g_x_lo[(size_t)BATCH * SLEN * DMODEL];
__device__ __align__(16) __half g_win_hi[3 * DMODEL * DMODEL];
__device__ __align__(16) __half g_wout_hi[DMODEL * DMODEL];
__device__ __align__(16) __half g_qkv_hi[(size_t)3 * NWIN * NHEADS * WIN * HD];
__device__ __align__(16) __half g_q_lo[(size_t)NWIN * NHEADS * WIN * HD];   // lo only for Q
__device__ __align__(16) __half g_o_hi[(size_t)NWIN * WIN * DMODEL];
__device__ __align__(16) __half g_o_lo[(size_t)NWIN * WIN * DMODEL];

// ---------------------------------------------------------------------------
// wmma fp16 types + 2-term split MMA
// ---------------------------------------------------------------------------
using HA  = wmma::fragment<wmma::matrix_a, 16, 16, 16, __half, wmma::row_major>;
using HBc = wmma::fragment<wmma::matrix_b, 16, 16, 16, __half, wmma::col_major>;
using HBr = wmma::fragment<wmma::matrix_b, 16, 16, 16, __half, wmma::row_major>;
using CF  = wmma::fragment<wmma::accumulator, 16, 16, 16, float>;

template <class FB>
__device__ __forceinline__ void mma2(CF& acc, const HA& ah, const HA& al, const FB& bh) {
    wmma::mma_sync(acc, al, bh, acc);
    wmma::mma_sync(acc, ah, bh, acc);
}

__device__ __forceinline__ void split_store4(const float4 v, __half* hi, __half* lo) {
    __half hx = __float2half_rn(v.x), hy = __float2half_rn(v.y);
    __half hz = __float2half_rn(v.z), hw = __float2half_rn(v.w);
    *reinterpret_cast<__half2*>(hi)     = __halves2half2(hx, hy);
    *reinterpret_cast<__half2*>(hi + 2) = __halves2half2(hz, hw);
    __half lx = __float2half_rn(v.x - __half2float(hx));
    __half ly = __float2half_rn(v.y - __half2float(hy));
    __half lz = __float2half_rn(v.z - __half2float(hz));
    __half lw = __float2half_rn(v.w - __half2float(hw));
    *reinterpret_cast<__half2*>(lo)     = __halves2half2(lx, ly);
    *reinterpret_cast<__half2*>(lo + 2) = __halves2half2(lz, lw);
}
__device__ __forceinline__ void hi_store4(const float4 v, __half* hi) {
    *reinterpret_cast<__half2*>(hi)     = __halves2half2(__float2half_rn(v.x), __float2half_rn(v.y));
    *reinterpret_cast<__half2*>(hi + 2) = __halves2half2(__float2half_rn(v.z), __float2half_rn(v.w));
}

// ---------------------------------------------------------------------------
// cp.async helpers
// ---------------------------------------------------------------------------
__device__ __forceinline__ uint32_t smem_to_u32(const void* p) {
    uint32_t a;
    asm("{ .reg .u64 t; cvta.to.shared.u64 t, %1; cvt.u32.u64 %0, t; }" : "=r"(a) : "l"(p));
    return a;
}
#define CP_ASYNC16(su32, gptr) \
    asm volatile("cp.async.cg.shared.global [%0], [%1], 16;" :: "r"(su32), "l"(gptr) : "memory")
#define CP_COMMIT() asm volatile("cp.async.commit_group;" ::: "memory")
#define CP_WAIT(n)  asm volatile("cp.async.wait_group %0;" :: "n"(n) : "memory")

// ---------------------------------------------------------------------------
// Prep splits. which: 0 = x (hi+lo), 1 = w_in (hi only), 2 = w_out (hi only)
// ---------------------------------------------------------------------------
__global__ void k_split(const float4* __restrict__ src, int which, int n4) {
    int i = blockIdx.x * blockDim.x + threadIdx.x;
    if (i >= n4) return;
    float4 v = src[i];
    if (which == 0)      split_store4(v, g_x_hi + (size_t)i * 4, g_x_lo + (size_t)i * 4);
    else if (which == 1) hi_store4(v, g_win_hi + (size_t)i * 4);
    else                 hi_store4(v, g_wout_hi + (size_t)i * 4);
}

// ---------------------------------------------------------------------------
// Projection GEMM: C[128x128] per CTA = (Ah+Al) @ Bh^T, cp.async 2-stage.
// MODE 0: A = rolled x, B = w_in -> g_qkv (hi; +lo for Q part), +b_in
// MODE 1: A = g_o,     B = w_out -> fp32 out with roll(+shift), +b_out
// smem per stage: Ah/Al/Bh [128][72] halves = 55296 B. 2 stages = 110592 B.
// Cs fp32 [128][132] overlays.
// ---------------------------------------------------------------------------
#define STG_BYTES 55296
#define PROJ_SMEM (2 * STG_BYTES)

template <int MODE>
__global__ __launch_bounds__(256, 2) void k_proj(const float* __restrict__ bias,
                                                 float* __restrict__ outp) {
    extern __shared__ char smem[];
    const uint32_t sb0 = smem_to_u32(smem);
    float* Cs = (float*)smem;              // [128][132]

    const int tid  = threadIdx.x;
    const int warp = tid >> 5;
    const int wr = warp >> 1, wc = warp & 1;   // 4x2 warp grid, 32x64 warp tiles
    const int n0 = blockIdx.x * 128;
    const int w  = blockIdx.y;
    const int b  = w >> 5, j = w & 31;

    const __half* Asrc_h = (MODE == 0) ? g_x_hi : g_o_hi;
    const __half* Asrc_l = (MODE == 0) ? g_x_lo : g_o_lo;
    const __half* Bsrc_h = (MODE == 0) ? g_win_hi : g_wout_hi;

    // loader mapping: 2 threads per row, 4 x 16B per array each
    const int lr = tid >> 1, c16b = (tid & 1) * 4;
    size_t arow;
    if (MODE == 0) {
        int sp = (j * WIN + lr + SHIFT) & (SLEN - 1);      // roll(-shift) gather
        arow = ((size_t)b * SLEN + sp) * DMODEL;
    } else {
        arow = ((size_t)w * WIN + lr) * DMODEL;
    }
    const size_t brow = (size_t)(n0 + lr) * DMODEL;

    CF acc[2][4];
#pragma unroll
    for (int i = 0; i < 2; i++)
#pragma unroll
        for (int jj = 0; jj < 4; jj++) wmma::fill_fragment(acc[i][jj], 0.0f);

    // prologue: chunk 0 -> stage 0
    {
        uint32_t sbase = sb0;
#pragma unroll
        for (int q = 0; q < 4; q++) {
            int c16 = c16b + q;
            uint32_t off = (uint32_t)(lr * 144 + c16 * 16);
            CP_ASYNC16(sbase + off,         Asrc_h + arow + c16 * 8);
            CP_ASYNC16(sbase + 18432 + off, Asrc_l + arow + c16 * 8);
            CP_ASYNC16(sbase + 36864 + off, Bsrc_h + brow + c16 * 8);
        }
        CP_COMMIT();
    }

    for (int c = 0; c < 8; c++) {
        if (c < 7) {           // prefetch chunk c+1 into opposite stage
            uint32_t sbase = sb0 + ((c + 1) & 1) * STG_BYTES;
            const size_t g = (size_t)(c + 1) * 64;
#pragma unroll
            for (int q = 0; q < 4; q++) {
                int c16 = c16b + q;
                uint32_t off = (uint32_t)(lr * 144 + c16 * 16);
                CP_ASYNC16(sbase + off,         Asrc_h + arow + g + c16 * 8);
                CP_ASYNC16(sbase + 18432 + off, Asrc_l + arow + g + c16 * 8);
                CP_ASYNC16(sbase + 36864 + off, Bsrc_h + brow + g + c16 * 8);
            }
            CP_COMMIT();
            CP_WAIT(1);
        } else {
            CP_WAIT(0);
        }
        __syncthreads();

        const __half* Ah = (const __half*)(smem + (c & 1) * STG_BYTES);
        const __half* Al = Ah + 9216;
        const __half* Bh = Ah + 18432;
#pragma unroll
        for (int ks = 0; ks < 4; ks++) {
            HA ah[2], al[2];
#pragma unroll
            for (int i = 0; i < 2; i++) {
                wmma::load_matrix_sync(ah[i], Ah + (wr * 32 + i * 16) * 72 + ks * 16, 72);
                wmma::load_matrix_sync(al[i], Al + (wr * 32 + i * 16) * 72 + ks * 16, 72);
            }
#pragma unroll
            for (int jj = 0; jj < 4; jj++) {
                HBc bh;
                wmma::load_matrix_sync(bh, Bh + (wc * 64 + jj * 16) * 72 + ks * 16, 72);
#pragma unroll
                for (int i = 0; i < 2; i++) mma2(acc[i][jj], ah[i], al[i], bh);
            }
        }
        __syncthreads();    // readers done before this stage is refilled
    }

#pragma unroll
    for (int i = 0; i < 2; i++)
#pragma unroll
        for (int jj = 0; jj < 4; jj++)
            wmma::store_matrix_sync(Cs + (wr * 32 + i * 16) * 132 + wc * 64 + jj * 16,
                                    acc[i][jj], 132, wmma::mem_row_major);
    __syncthreads();

#pragma unroll
    for (int it = 0; it < 16; it++) {
        int idx = tid + it * 256;          // 128 rows x 32 col-groups
        int r = idx >> 5, cc = (idx & 31) * 4;
        float4 v;
        v.x = Cs[r * 132 + cc + 0] + bias[n0 + cc + 0];
        v.y = Cs[r * 132 + cc + 1] + bias[n0 + cc + 1];
        v.z = Cs[r * 132 + cc + 2] + bias[n0 + cc + 2];
        v.w = Cs[r * 132 + cc + 3] + bias[n0 + cc + 3];
        if (MODE == 0) {
            int gc = n0 + cc;
            int p = gc >> 9, hh = (gc >> 6) & 7, d = gc & 63;
            size_t o = ((((size_t)p * NWIN + w) * NHEADS + hh) * WIN + r) * HD + d;
            if (p == 0) split_store4(v, g_qkv_hi + o, g_q_lo + o);
            else        hi_store4(v, g_qkv_hi + o);
        } else {
            int sp = (j * WIN + r + SHIFT) & (SLEN - 1);   // roll(+shift) scatter
            *(float4*)(outp + ((size_t)b * SLEN + sp) * DMODEL + n0 + cc) = v;
        }
    }
}

// ---------------------------------------------------------------------------
// Attention: one CTA per (window, head), 512 threads.
// smem (half offsets):  Qh 0, Ql 9216, Kh 18432  | Ps fp32 overlay [0,33792)
//   Vh 33792, Ph 43008 [128][136], Pl 60416      | Os fp32 overlay [0,17408)
// total halves 77824 -> 155648 B
// ---------------------------------------------------------------------------
#define ATTN_SMEM 155648

__global__ __launch_bounds__(512, 1) void k_attn() {
    extern __shared__ __half smh[];
    __half* Qh = smh;
    __half* Ql = smh + 9216;
    __half* Kh = smh + 18432;
    float*  Ps = (float*)smh;                  // [128][132]
    __half* Vh = smh + 33792;
    __half* Ph = smh + 43008;                  // [128][136]
    __half* Pl = smh + 60416;
    float*  Os = (float*)smh;                  // [128][68]

    const int w = blockIdx.x, h = blockIdx.y;
    const int tid = threadIdx.x;
    const int warp = tid >> 5, lane = tid & 31;

    const size_t part = (size_t)NWIN * NHEADS * WIN * HD;
    const size_t bq = ((size_t)w * NHEADS + h) * (WIN * HD);

    {   // loads: 4 threads per row, 16 halves (2 x uint4) each
        const int r = tid >> 2, cg = (tid & 3) * 16;
        const size_t so = bq + (size_t)r * HD + cg;
        const int dst = r * 72 + cg;
        *(uint4*)&Qh[dst]     = *(const uint4*)(g_qkv_hi + so);
        *(uint4*)&Qh[dst + 8] = *(const uint4*)(g_qkv_hi + so + 8);
        *(uint4*)&Ql[dst]     = *(const uint4*)(g_q_lo + so);
        *(uint4*)&Ql[dst + 8] = *(const uint4*)(g_q_lo + so + 8);
        *(uint4*)&Kh[dst]     = *(const uint4*)(g_qkv_hi + part + so);
        *(uint4*)&Kh[dst + 8] = *(const uint4*)(g_qkv_hi + part + so + 8);
        *(uint4*)&Vh[dst]     = *(const uint4*)(g_qkv_hi + 2 * part + so);
        *(uint4*)&Vh[dst + 8] = *(const uint4*)(g_qkv_hi + 2 * part + so + 8);
    }
    __syncthreads();

    // ---- S = Q K^T / 8 : 16 warps, 4x4 grid, 32x32 tiles ----
    {
        const int wrS = warp >> 2, wcS = warp & 3;
        CF sacc[2][2];
#pragma unroll
        for (int i = 0; i < 2; i++)
#pragma unroll
            for (int jj = 0; jj < 2; jj++) wmma::fill_fragment(sacc[i][jj], 0.0f);
#pragma unroll
        for (int kk = 0; kk < 4; kk++) {
            HA qh2[2], ql2[2];
#pragma unroll
            for (int i = 0; i < 2; i++) {
                wmma::load_matrix_sync(qh2[i], Qh + (wrS * 32 + i * 16) * 72 + kk * 16, 72);
                wmma::load_matrix_sync(ql2[i], Ql + (wrS * 32 + i * 16) * 72 + kk * 16, 72);
            }
#pragma unroll
            for (int jj = 0; jj < 2; jj++) {
                HBc kh2;
                wmma::load_matrix_sync(kh2, Kh + (wcS * 32 + jj * 16) * 72 + kk * 16, 72);
#pragma unroll
                for (int i = 0; i < 2; i++) mma2(sacc[i][jj], qh2[i], ql2[i], kh2);
            }
        }
        __syncthreads();   // Q/K reads complete before Ps overlays
#pragma unroll
        for (int i = 0; i < 2; i++)
#pragma unroll
            for (int jj = 0; jj < 2; jj++) {
#pragma unroll
                for (int e = 0; e < sacc[i][jj].num_elements; e++) sacc[i][jj].x[e] *= 0.125f;
                wmma::store_matrix_sync(Ps + (wrS * 32 + i * 16) * 132 + wcS * 32 + jj * 16,
                                        sacc[i][jj], 132, wmma::mem_row_major);
            }
    }
    __syncthreads();

    // ---- softmax: 16 warps x 8 rows, write fp16 hi/lo P ----
#pragma unroll
    for (int rr = 0; rr < 8; rr++) {
        const int row = warp * 8 + rr;
        const float* prow = Ps + row * 132;
        float v0 = prow[lane], v1 = prow[lane + 32], v2 = prow[lane + 64], v3 = prow[lane + 96];
        float m = fmaxf(fmaxf(v0, v1), fmaxf(v2, v3));
#pragma unroll
        for (int o = 16; o; o >>= 1) m = fmaxf(m, __shfl_xor_sync(0xffffffffu, m, o));
        v0 = __expf(v0 - m); v1 = __expf(v1 - m); v2 = __expf(v2 - m); v3 = __expf(v3 - m);
        float s = v0 + v1 + v2 + v3;
#pragma unroll
        for (int o = 16; o; o >>= 1) s += __shfl_xor_sync(0xffffffffu, s, o);
        float inv = 1.0f / s;
        __half* ph = Ph + row * 136;
        __half* pl = Pl + row * 136;
#pragma unroll
        for (int q = 0; q < 4; q++) {
            float p = ((q == 0) ? v0 : (q == 1) ? v1 : (q == 2) ? v2 : v3) * inv;
            __half hp = __float2half_rn(p);
            ph[lane + q * 32] = hp;
            pl[lane + q * 32] = __float2half_rn(p - __half2float(hp));
        }
    }
    __syncthreads();

    // ---- O = P V : 16 warps, 8x2 grid, 16x32 tiles ----
    {
        const int wrP = warp >> 1, wcP = warp & 1;
        CF oacc[2];
        wmma::fill_fragment(oacc[0], 0.0f);
        wmma::fill_fragment(oacc[1], 0.0f);
#pragma unroll
        for (int kk = 0; kk < 8; kk++) {
            HA ph2, pl2;
            wmma::load_matrix_sync(ph2, Ph + (wrP * 16) * 136 + kk * 16, 136);
            wmma::load_matrix_sync(pl2, Pl + (wrP * 16) * 136 + kk * 16, 136);
#pragma unroll
            for (int jj = 0; jj < 2; jj++) {
                HBr vh2;
                wmma::load_matrix_sync(vh2, Vh + (kk * 16) * 72 + wcP * 32 + jj * 16, 72);
                mma2(oacc[jj], ph2, pl2, vh2);
            }
        }
        __syncthreads();   // V reads (and Ps region) done before Os overlay
#pragma unroll
        for (int jj = 0; jj < 2; jj++)
            wmma::store_matrix_sync(Os + (wrP * 16) * 68 + wcP * 32 + jj * 16,
                                    oacc[jj], 68, wmma::mem_row_major);
    }
    __syncthreads();

    // ---- split-store O to g_o hi/lo ----
#pragma unroll
    for (int it = 0; it < 4; it++) {
        int idx = tid + it * 512;          // 128 rows x 16 col-groups
        int r = idx >> 4, cc = (idx & 15) * 4;
        float4 v;
        v.x = Os[r * 68 + cc + 0];
        v.y = Os[r * 68 + cc + 1];
        v.z = Os[r * 68 + cc + 2];
        v.w = Os[r * 68 + cc + 3];
        size_t o = ((size_t)w * WIN + r) * DMODEL + h * HD + cc;
        split_store4(v, g_o_hi + o, g_o_lo + o);
    }
}

// ---------------------------------------------------------------------------
extern "C" void kernel_launch(void* const* d_in, const int* in_sizes, int n_in,
                              void* d_out, int out_size) {
    const float* x     = (const float*)d_in[0];
    const float* w_in  = (const float*)d_in[1];
    const float* b_in  = (const float*)d_in[2];
    const float* w_out = (const float*)d_in[3];
    const float* b_out = (const float*)d_in[4];
    float* out = (float*)d_out;

    cudaFuncSetAttribute(k_proj<0>, cudaFuncAttributeMaxDynamicSharedMemorySize, PROJ_SMEM);
    cudaFuncSetAttribute(k_proj<1>, cudaFuncAttributeMaxDynamicSharedMemorySize, PROJ_SMEM);
    cudaFuncSetAttribute(k_attn,    cudaFuncAttributeMaxDynamicSharedMemorySize, ATTN_SMEM);

    const int n4x  = BATCH * SLEN * DMODEL / 4;     // 16,777,216
    const int n4wi = 3 * DMODEL * DMODEL / 4;       // 196,608
    const int n4wo = DMODEL * DMODEL / 4;           // 65,536
    k_split<<<n4x / 256, 256>>>((const float4*)x, 0, n4x);
    k_split<<<n4wi / 256, 256>>>((const float4*)w_in, 1, n4wi);
    k_split<<<n4wo / 256, 256>>>((const float4*)w_out, 2, n4wo);

    k_proj<0><<<dim3(12, NWIN), 256, PROJ_SMEM>>>(b_in, nullptr);
    k_attn<<<dim3(NWIN, NHEADS), 512, ATTN_SMEM>>>();
    k_proj<1><<<dim3(4, NWIN), 256, PROJ_SMEM>>>(b_out, out);
}

// round 5
// speedup vs baseline: 4.9633x; 1.2004x over previous
#include <cuda_runtime.h>
#include <cuda_fp16.h>
#include <mma.h>
#include <cstdint>
using namespace nvcuda;

// Problem constants (fixed by setup_inputs)
#define BATCH   32
#define SLEN    4096
#define DMODEL  512
#define NHEADS  8
#define HD      64
#define WIN     128
#define SHIFT   64
#define NWIN    1024          // total windows (BATCH * 32)

// ---------------------------------------------------------------------------
// Persistent fp16 arrays. Activations (A-side) keep hi/lo split; weights and
// the B-side of attention (K, V) keep hi only (2-term split: (Ah+Al)*Bh).
// ---------------------------------------------------------------------------
__device__ __align__(16) __half g_x_hi[(size_t)BATCH * SLEN * DMODEL];
__device__ __align__(16) __half g_x_lo[(size_t)BATCH * SLEN * DMODEL];
__device__ __align__(16) __half g_win_hi[3 * DMODEL * DMODEL];
__device__ __align__(16) __half g_wout_hi[DMODEL * DMODEL];
__device__ __align__(16) __half g_qkv_hi[(size_t)3 * NWIN * NHEADS * WIN * HD];
__device__ __align__(16) __half g_q_lo[(size_t)NWIN * NHEADS * WIN * HD];   // lo only for Q
__device__ __align__(16) __half g_o_hi[(size_t)NWIN * WIN * DMODEL];
__device__ __align__(16) __half g_o_lo[(size_t)NWIN * WIN * DMODEL];

// ---------------------------------------------------------------------------
// wmma fp16 types + 2-term split MMA
// ---------------------------------------------------------------------------
using HA  = wmma::fragment<wmma::matrix_a, 16, 16, 16, __half, wmma::row_major>;
using HBc = wmma::fragment<wmma::matrix_b, 16, 16, 16, __half, wmma::col_major>;
using HBr = wmma::fragment<wmma::matrix_b, 16, 16, 16, __half, wmma::row_major>;
using CF  = wmma::fragment<wmma::accumulator, 16, 16, 16, float>;

template <class FB>
__device__ __forceinline__ void mma2(CF& acc, const HA& ah, const HA& al, const FB& bh) {
    wmma::mma_sync(acc, al, bh, acc);
    wmma::mma_sync(acc, ah, bh, acc);
}

__device__ __forceinline__ void split_store4(const float4 v, __half* hi, __half* lo) {
    __half hx = __float2half_rn(v.x), hy = __float2half_rn(v.y);
    __half hz = __float2half_rn(v.z), hw = __float2half_rn(v.w);
    *reinterpret_cast<__half2*>(hi)     = __halves2half2(hx, hy);
    *reinterpret_cast<__half2*>(hi + 2) = __halves2half2(hz, hw);
    __half lx = __float2half_rn(v.x - __half2float(hx));
    __half ly = __float2half_rn(v.y - __half2float(hy));
    __half lz = __float2half_rn(v.z - __half2float(hz));
    __half lw = __float2half_rn(v.w - __half2float(hw));
    *reinterpret_cast<__half2*>(lo)     = __halves2half2(lx, ly);
    *reinterpret_cast<__half2*>(lo + 2) = __halves2half2(lz, lw);
}
__device__ __forceinline__ void hi_store4(const float4 v, __half* hi) {
    *reinterpret_cast<__half2*>(hi)     = __halves2half2(__float2half_rn(v.x), __float2half_rn(v.y));
    *reinterpret_cast<__half2*>(hi + 2) = __halves2half2(__float2half_rn(v.z), __float2half_rn(v.w));
}

// ---------------------------------------------------------------------------
// cp.async helpers
// ---------------------------------------------------------------------------
__device__ __forceinline__ uint32_t smem_to_u32(const void* p) {
    uint32_t a;
    asm("{ .reg .u64 t; cvta.to.shared.u64 t, %1; cvt.u32.u64 %0, t; }" : "=r"(a) : "l"(p));
    return a;
}
#define CP_ASYNC16(su32, gptr) \
    asm volatile("cp.async.cg.shared.global [%0], [%1], 16;" :: "r"(su32), "l"(gptr) : "memory")
#define CP_COMMIT() asm volatile("cp.async.commit_group;" ::: "memory")
#define CP_WAIT(n)  asm volatile("cp.async.wait_group %0;" :: "n"(n) : "memory")

// ---------------------------------------------------------------------------
// Prep splits. which: 0 = x (hi+lo), 1 = w_in (hi only), 2 = w_out (hi only)
// ---------------------------------------------------------------------------
__global__ void k_split(const float4* __restrict__ src, int which, int n4) {
    int i = blockIdx.x * blockDim.x + threadIdx.x;
    if (i >= n4) return;
    float4 v = src[i];
    if (which == 0)      split_store4(v, g_x_hi + (size_t)i * 4, g_x_lo + (size_t)i * 4);
    else if (which == 1) hi_store4(v, g_win_hi + (size_t)i * 4);
    else                 hi_store4(v, g_wout_hi + (size_t)i * 4);
}

// ---------------------------------------------------------------------------
// Projection GEMM: C[128x256] per CTA = (Ah+Al) @ Bh^T, cp.async 2-stage.
// 512 threads, warp grid 4x4 (warp tile 32x64).
// MODE 0: A = rolled x, B = w_in -> g_qkv (hi; +lo for Q part), +b_in
// MODE 1: A = g_o,     B = w_out -> fp32 out with roll(+shift), +b_out
// smem per stage: Ah[128][72] Al[128][72] Bh[256][72] halves = 73728 B.
// 2 stages = 147456 B. Cs fp32 [128][264] (135168 B) overlays.
// ---------------------------------------------------------------------------
#define STG_BYTES 73728
#define PROJ_SMEM (2 * STG_BYTES)

template <int MODE>
__global__ __launch_bounds__(512, 1) void k_proj(const float* __restrict__ bias,
                                                 float* __restrict__ outp) {
    extern __shared__ char smem[];
    const uint32_t sb0 = smem_to_u32(smem);
    float* Cs = (float*)smem;              // [128][264]

    const int tid  = threadIdx.x;
    const int warp = tid >> 5;
    const int wr = warp >> 2, wc = warp & 3;   // 4x4 warp grid, 32x64 warp tiles
    const int n0 = blockIdx.x * 256;
    const int w  = blockIdx.y;
    const int b  = w >> 5, j = w & 31;

    const __half* Asrc_h = (MODE == 0) ? g_x_hi : g_o_hi;
    const __half* Asrc_l = (MODE == 0) ? g_x_lo : g_o_lo;
    const __half* Bsrc_h = (MODE == 0) ? g_win_hi : g_wout_hi;

    // Per-window A base (row added per cp.async below)
    const size_t abase = (MODE == 0) ? ((size_t)b * SLEN) * DMODEL
                                     : ((size_t)w * WIN) * DMODEL;

    CF acc[2][4];
#pragma unroll
    for (int i = 0; i < 2; i++)
#pragma unroll
        for (int jj = 0; jj < 4; jj++) wmma::fill_fragment(acc[i][jj], 0.0f);

    // ---- async load of one chunk (64 halves of K) into stage `st` ----
    auto load_chunk = [&](int c, int st) {
        const uint32_t sbase = sb0 + st * STG_BYTES;
        const size_t g = (size_t)c * 64;
#pragma unroll
        for (int q = 0; q < 2; q++) {          // A: 128 rows x 8 c16 = 1024
            int idx = tid + q * 512;
            int row = idx >> 3, c16 = idx & 7;
            size_t ar;
            if (MODE == 0) {
                int sp = (j * WIN + row + SHIFT) & (SLEN - 1);   // roll(-shift)
                ar = abase + (size_t)sp * DMODEL + g + c16 * 8;
            } else {
                ar = abase + (size_t)row * DMODEL + g + c16 * 8;
            }
            uint32_t off = (uint32_t)(row * 144 + c16 * 16);
            CP_ASYNC16(sbase + off,         Asrc_h + ar);
            CP_ASYNC16(sbase + 18432 + off, Asrc_l + ar);
        }
#pragma unroll
        for (int q = 0; q < 4; q++) {          // B: 256 rows x 8 c16 = 2048
            int idx = tid + q * 512;
            int row = idx >> 3, c16 = idx & 7;
            size_t br = (size_t)(n0 + row) * DMODEL + g + c16 * 8;
            CP_ASYNC16(sbase + 36864 + (uint32_t)(row * 144 + c16 * 16), Bsrc_h + br);
        }
        CP_COMMIT();
    };

    load_chunk(0, 0);                          // prologue

    for (int c = 0; c < 8; c++) {
        if (c < 7) { load_chunk(c + 1, (c + 1) & 1); CP_WAIT(1); }
        else       { CP_WAIT(0); }
        __syncthreads();

        const __half* Ah = (const __half*)(smem + (c & 1) * STG_BYTES);
        const __half* Al = Ah + 9216;
        const __half* Bh = Ah + 18432;
#pragma unroll
        for (int ks = 0; ks < 4; ks++) {
            HA ah[2], al[2];
#pragma unroll
            for (int i = 0; i < 2; i++) {
                wmma::load_matrix_sync(ah[i], Ah + (wr * 32 + i * 16) * 72 + ks * 16, 72);
                wmma::load_matrix_sync(al[i], Al + (wr * 32 + i * 16) * 72 + ks * 16, 72);
            }
#pragma unroll
            for (int jj = 0; jj < 4; jj++) {
                HBc bh;
                wmma::load_matrix_sync(bh, Bh + (wc * 64 + jj * 16) * 72 + ks * 16, 72);
#pragma unroll
                for (int i = 0; i < 2; i++) mma2(acc[i][jj], ah[i], al[i], bh);
            }
        }
        __syncthreads();    // readers done before this stage is refilled
    }

#pragma unroll
    for (int i = 0; i < 2; i++)
#pragma unroll
        for (int jj = 0; jj < 4; jj++)
            wmma::store_matrix_sync(Cs + (wr * 32 + i * 16) * 264 + wc * 64 + jj * 16,
                                    acc[i][jj], 264, wmma::mem_row_major);
    __syncthreads();

#pragma unroll
    for (int it = 0; it < 16; it++) {
        int idx = tid + it * 512;              // 128 rows x 64 col-groups
        int r = idx >> 6, cc = (idx & 63) * 4;
        float4 v;
        v.x = Cs[r * 264 + cc + 0] + bias[n0 + cc + 0];
        v.y = Cs[r * 264 + cc + 1] + bias[n0 + cc + 1];
        v.z = Cs[r * 264 + cc + 2] + bias[n0 + cc + 2];
        v.w = Cs[r * 264 + cc + 3] + bias[n0 + cc + 3];
        if (MODE == 0) {
            int gc = n0 + cc;
            int p = gc >> 9, hh = (gc >> 6) & 7, d = gc & 63;
            size_t o = ((((size_t)p * NWIN + w) * NHEADS + hh) * WIN + r) * HD + d;
            if (p == 0) split_store4(v, g_qkv_hi + o, g_q_lo + o);
            else        hi_store4(v, g_qkv_hi + o);
        } else {
            int sp = (j * WIN + r + SHIFT) & (SLEN - 1);   // roll(+shift) scatter
            *(float4*)(outp + ((size_t)b * SLEN + sp) * DMODEL + n0 + cc) = v;
        }
    }
}

// ---------------------------------------------------------------------------
// Attention: one CTA per (window, head), 512 threads.
// smem (half offsets):  Qh 0, Ql 9216, Kh 18432  | Ps fp32 overlay [0,33792)
//   Vh 33792, Ph 43008 [128][136], Pl 60416      | Os fp32 overlay [0,17408)
// total halves 77824 -> 155648 B
// ---------------------------------------------------------------------------
#define ATTN_SMEM 155648

__global__ __launch_bounds__(512, 1) void k_attn() {
    extern __shared__ __half smh[];
    __half* Qh = smh;
    __half* Ql = smh + 9216;
    __half* Kh = smh + 18432;
    float*  Ps = (float*)smh;                  // [128][132]
    __half* Vh = smh + 33792;
    __half* Ph = smh + 43008;                  // [128][136]
    __half* Pl = smh + 60416;
    float*  Os = (float*)smh;                  // [128][68]

    const int w = blockIdx.x, h = blockIdx.y;
    const int tid = threadIdx.x;
    const int warp = tid >> 5, lane = tid & 31;

    const size_t part = (size_t)NWIN * NHEADS * WIN * HD;
    const size_t bq = ((size_t)w * NHEADS + h) * (WIN * HD);

    {   // loads: 4 threads per row, 16 halves (2 x uint4) each
        const int r = tid >> 2, cg = (tid & 3) * 16;
        const size_t so = bq + (size_t)r * HD + cg;
        const int dst = r * 72 + cg;
        *(uint4*)&Qh[dst]     = *(const uint4*)(g_qkv_hi + so);
        *(uint4*)&Qh[dst + 8] = *(const uint4*)(g_qkv_hi + so + 8);
        *(uint4*)&Ql[dst]     = *(const uint4*)(g_q_lo + so);
        *(uint4*)&Ql[dst + 8] = *(const uint4*)(g_q_lo + so + 8);
        *(uint4*)&Kh[dst]     = *(const uint4*)(g_qkv_hi + part + so);
        *(uint4*)&Kh[dst + 8] = *(const uint4*)(g_qkv_hi + part + so + 8);
        *(uint4*)&Vh[dst]     = *(const uint4*)(g_qkv_hi + 2 * part + so);
        *(uint4*)&Vh[dst + 8] = *(const uint4*)(g_qkv_hi + 2 * part + so + 8);
    }
    __syncthreads();

    // ---- S = Q K^T / 8 : 16 warps, 4x4 grid, 32x32 tiles ----
    {
        const int wrS = warp >> 2, wcS = warp & 3;
        CF sacc[2][2];
#pragma unroll
        for (int i = 0; i < 2; i++)
#pragma unroll
            for (int jj = 0; jj < 2; jj++) wmma::fill_fragment(sacc[i][jj], 0.0f);
#pragma unroll
        for (int kk = 0; kk < 4; kk++) {
            HA qh2[2], ql2[2];
#pragma unroll
            for (int i = 0; i < 2; i++) {
                wmma::load_matrix_sync(qh2[i], Qh + (wrS * 32 + i * 16) * 72 + kk * 16, 72);
                wmma::load_matrix_sync(ql2[i], Ql + (wrS * 32 + i * 16) * 72 + kk * 16, 72);
            }
#pragma unroll
            for (int jj = 0; jj < 2; jj++) {
                HBc kh2;
                wmma::load_matrix_sync(kh2, Kh + (wcS * 32 + jj * 16) * 72 + kk * 16, 72);
#pragma unroll
                for (int i = 0; i < 2; i++) mma2(sacc[i][jj], qh2[i], ql2[i], kh2);
            }
        }
        __syncthreads();   // Q/K reads complete before Ps overlays
#pragma unroll
        for (int i = 0; i < 2; i++)
#pragma unroll
            for (int jj = 0; jj < 2; jj++) {
#pragma unroll
                for (int e = 0; e < sacc[i][jj].num_elements; e++) sacc[i][jj].x[e] *= 0.125f;
                wmma::store_matrix_sync(Ps + (wrS * 32 + i * 16) * 132 + wcS * 32 + jj * 16,
                                        sacc[i][jj], 132, wmma::mem_row_major);
            }
    }
    __syncthreads();

    // ---- softmax: 16 warps x 8 rows, write fp16 hi/lo P ----
#pragma unroll
    for (int rr = 0; rr < 8; rr++) {
        const int row = warp * 8 + rr;
        const float* prow = Ps + row * 132;
        float v0 = prow[lane], v1 = prow[lane + 32], v2 = prow[lane + 64], v3 = prow[lane + 96];
        float m = fmaxf(fmaxf(v0, v1), fmaxf(v2, v3));
#pragma unroll
        for (int o = 16; o; o >>= 1) m = fmaxf(m, __shfl_xor_sync(0xffffffffu, m, o));
        v0 = __expf(v0 - m); v1 = __expf(v1 - m); v2 = __expf(v2 - m); v3 = __expf(v3 - m);
        float s = v0 + v1 + v2 + v3;
#pragma unroll
        for (int o = 16; o; o >>= 1) s += __shfl_xor_sync(0xffffffffu, s, o);
        float inv = 1.0f / s;
        __half* ph = Ph + row * 136;
        __half* pl = Pl + row * 136;
#pragma unroll
        for (int q = 0; q < 4; q++) {
            float p = ((q == 0) ? v0 : (q == 1) ? v1 : (q == 2) ? v2 : v3) * inv;
            __half hp = __float2half_rn(p);
            ph[lane + q * 32] = hp;
            pl[lane + q * 32] = __float2half_rn(p - __half2float(hp));
        }
    }
    __syncthreads();

    // ---- O = P V : 16 warps, 8x2 grid, 16x32 tiles ----
    {
        const int wrP = warp >> 1, wcP = warp & 1;
        CF oacc[2];
        wmma::fill_fragment(oacc[0], 0.0f);
        wmma::fill_fragment(oacc[1], 0.0f);
#pragma unroll
        for (int kk = 0; kk < 8; kk++) {
            HA ph2, pl2;
            wmma::load_matrix_sync(ph2, Ph + (wrP * 16) * 136 + kk * 16, 136);
            wmma::load_matrix_sync(pl2, Pl + (wrP * 16) * 136 + kk * 16, 136);
#pragma unroll
            for (int jj = 0; jj < 2; jj++) {
                HBr vh2;
                wmma::load_matrix_sync(vh2, Vh + (kk * 16) * 72 + wcP * 32 + jj * 16, 72);
                mma2(oacc[jj], ph2, pl2, vh2);
            }
        }
        __syncthreads();   // V reads (and Ps region) done before Os overlay
#pragma unroll
        for (int jj = 0; jj < 2; jj++)
            wmma::store_matrix_sync(Os + (wrP * 16) * 68 + wcP * 32 + jj * 16,
                                    oacc[jj], 68, wmma::mem_row_major);
    }
    __syncthreads();

    // ---- split-store O to g_o hi/lo ----
#pragma unroll
    for (int it = 0; it < 4; it++) {
        int idx = tid + it * 512;          // 128 rows x 16 col-groups
        int r = idx >> 4, cc = (idx & 15) * 4;
        float4 v;
        v.x = Os[r * 68 + cc + 0];
        v.y = Os[r * 68 + cc + 1];
        v.z = Os[r * 68 + cc + 2];
        v.w = Os[r * 68 + cc + 3];
        size_t o = ((size_t)w * WIN + r) * DMODEL + h * HD + cc;
        split_store4(v, g_o_hi + o, g_o_lo + o);
    }
}

// ---------------------------------------------------------------------------
extern "C" void kernel_launch(void* const* d_in, const int* in_sizes, int n_in,
                              void* d_out, int out_size) {
    const float* x     = (const float*)d_in[0];
    const float* w_in  = (const float*)d_in[1];
    const float* b_in  = (const float*)d_in[2];
    const float* w_out = (const float*)d_in[3];
    const float* b_out = (const float*)d_in[4];
    float* out = (float*)d_out;

    cudaFuncSetAttribute(k_proj<0>, cudaFuncAttributeMaxDynamicSharedMemorySize, PROJ_SMEM);
    cudaFuncSetAttribute(k_proj<1>, cudaFuncAttributeMaxDynamicSharedMemorySize, PROJ_SMEM);
    cudaFuncSetAttribute(k_attn,    cudaFuncAttributeMaxDynamicSharedMemorySize, ATTN_SMEM);

    const int n4x  = BATCH * SLEN * DMODEL / 4;     // 16,777,216
    const int n4wi = 3 * DMODEL * DMODEL / 4;       // 196,608
    const int n4wo = DMODEL * DMODEL / 4;           // 65,536
    k_split<<<n4x / 256, 256>>>((const float4*)x, 0, n4x);
    k_split<<<n4wi / 256, 256>>>((const float4*)w_in, 1, n4wi);
    k_split<<<n4wo / 256, 256>>>((const float4*)w_out, 2, n4wo);

    k_proj<0><<<dim3(6, NWIN), 512, PROJ_SMEM>>>(b_in, nullptr);
    k_attn<<<dim3(NWIN, NHEADS), 512, ATTN_SMEM>>>();
    k_proj<1><<<dim3(2, NWIN), 512, PROJ_SMEM>>>(b_out, out);
}